// round 2
// baseline (speedup 1.0000x reference)
#include <cuda_runtime.h>
#include <math.h>

#define NPTS 4096
#define DIM  64
#define LOG2E_F 1.4426950408889634f
#define LN2_F   0.6931471805599453f

// Cost matrices: 0 = C_xy, 1 = C_yx, 2 = C_xx, 3 = C_yy   (4 x 64 MB)
__device__ float g_C[4][(size_t)NPTS * NPTS];
__device__ float g_n2[2][NPTS];          // squared norms of x, y
__device__ float g_pot[2][4][NPTS];      // double-buffered potentials: f_ba, g_ab, f_aa, g_bb
__device__ float g_h2[4][NPTS];          // per-iteration h vectors in log2 domain
__device__ float g_fin[4][NPTS];         // final softmin outputs

// ---------------------------------------------------------------------------
// Squared norms
// ---------------------------------------------------------------------------
__global__ void norms_k(const float* __restrict__ x, const float* __restrict__ y) {
    int i = blockIdx.x * blockDim.x + threadIdx.x;
    if (i >= 2 * NPTS) return;
    const float* p = (i < NPTS) ? (x + (size_t)i * DIM) : (y + (size_t)(i - NPTS) * DIM);
    float s = 0.0f;
#pragma unroll
    for (int k = 0; k < DIM; k += 4) {
        float4 v = *(const float4*)&p[k];
        s += v.x * v.x + v.y * v.y + v.z * v.z + v.w * v.w;
    }
    g_n2[i >= NPTS ? 1 : 0][i & (NPTS - 1)] = s;
}

// ---------------------------------------------------------------------------
// Cost matrix: C[i][j] = 0.5*(|a_i|^2 + |b_j|^2) - a_i . b_j
// Block: 16x16 threads, 64x64 output tile, K=64 in one slab.
// ---------------------------------------------------------------------------
__global__ __launch_bounds__(256) void cost_k(const float* __restrict__ A,
                                              const float* __restrict__ B,
                                              int sel) {
    __shared__ float As[64][68];   // [k][r], row stride 272B (16B aligned)
    __shared__ float Bs[64][68];   // [k][c]

    int r0 = blockIdx.y * 64, c0 = blockIdx.x * 64;
    int tid = threadIdx.y * 16 + threadIdx.x;

#pragma unroll
    for (int p = 0; p < 4; p++) {
        int q  = tid + p * 256;        // float4 index 0..1023
        int r  = q >> 4;               // 16 float4 per 64-float row
        int kc = (q & 15) << 2;
        float4 va = *(const float4*)&A[(size_t)(r0 + r) * DIM + kc];
        As[kc + 0][r] = va.x; As[kc + 1][r] = va.y;
        As[kc + 2][r] = va.z; As[kc + 3][r] = va.w;
        float4 vb = *(const float4*)&B[(size_t)(c0 + r) * DIM + kc];
        Bs[kc + 0][r] = vb.x; Bs[kc + 1][r] = vb.y;
        Bs[kc + 2][r] = vb.z; Bs[kc + 3][r] = vb.w;
    }
    __syncthreads();

    float acc[4][4] = {};
    int ty4 = threadIdx.y * 4, tx4 = threadIdx.x * 4;
#pragma unroll 8
    for (int k = 0; k < 64; k++) {
        float4 a = *(const float4*)&As[k][ty4];
        float4 b = *(const float4*)&Bs[k][tx4];
        acc[0][0] += a.x * b.x; acc[0][1] += a.x * b.y; acc[0][2] += a.x * b.z; acc[0][3] += a.x * b.w;
        acc[1][0] += a.y * b.x; acc[1][1] += a.y * b.y; acc[1][2] += a.y * b.z; acc[1][3] += a.y * b.w;
        acc[2][0] += a.z * b.x; acc[2][1] += a.z * b.y; acc[2][2] += a.z * b.z; acc[2][3] += a.z * b.w;
        acc[3][0] += a.w * b.x; acc[3][1] += a.w * b.y; acc[3][2] += a.w * b.z; acc[3][3] += a.w * b.w;
    }

    const float* na = (sel == 0 || sel == 2) ? g_n2[0] : g_n2[1];
    const float* nb = (sel == 1 || sel == 2) ? g_n2[0] : g_n2[1];
    float* Cout = g_C[sel];

    float nbv[4];
#pragma unroll
    for (int jj = 0; jj < 4; jj++) nbv[jj] = 0.5f * nb[c0 + tx4 + jj];
#pragma unroll
    for (int ii = 0; ii < 4; ii++) {
        int i = r0 + ty4 + ii;
        float ni = 0.5f * na[i];
        float4 o;
        o.x = ni + nbv[0] - acc[ii][0];
        o.y = ni + nbv[1] - acc[ii][1];
        o.z = ni + nbv[2] - acc[ii][2];
        o.w = ni + nbv[3] - acc[ii][3];
        *(float4*)&Cout[(size_t)i * NPTS + c0 + tx4] = o;
    }
}

// ---------------------------------------------------------------------------
// Prepare h2[w][j] = (log_w + pot[j]*inv_eps) * LOG2E  for the 4 softmins.
// pot source per softmin w: {g_ab, f_ba, f_aa, g_bb} = g_pot[buf][{1,0,2,3}]
// ---------------------------------------------------------------------------
__global__ void prep_h2_k(int buf, float inv_eps, int init, float log_w) {
    int j  = blockIdx.x * blockDim.x + threadIdx.x;   // 0 .. 4*NPTS-1
    int w  = j >> 12;
    int jj = j & (NPTS - 1);
    int pw = (w == 0) ? 1 : (w == 1) ? 0 : w;
    float pot = init ? 0.0f : g_pot[buf][pw][jj];
    g_h2[w][jj] = fmaf(pot, inv_eps, log_w) * LOG2E_F;
}

// ---------------------------------------------------------------------------
// Fused 4-way softmin. Grid (NPTS, 4). One block = one row logsumexp.
// t_j = h2[j] - C[row][j]*ie2   (log2 domain);  ft = negEpsLn2 * (max + log2(sum))
// mode 0: raw -> g_pot[bufout]; mode 1: avg with g_pot[bufin] -> g_pot[bufout];
// mode 2: raw -> g_fin
// ---------------------------------------------------------------------------
__global__ __launch_bounds__(256) void softmin4_k(int bufin, int bufout,
                                                  float negEpsLn2, float ie2, int mode) {
    __shared__ float red[256];
    int w = blockIdx.y, row = blockIdx.x, tid = threadIdx.x;

    const float4* C4 = (const float4*)(g_C[w] + (size_t)row * NPTS);
    const float4* H4 = (const float4*)g_h2[w];

    float t[16];
    float m = -3.4e38f;
#pragma unroll
    for (int p = 0; p < 4; p++) {
        int q = tid + p * 256;
        float4 c = C4[q];
        float4 h = H4[q];
        float* tp = &t[p * 4];
        tp[0] = fmaf(-ie2, c.x, h.x);
        tp[1] = fmaf(-ie2, c.y, h.y);
        tp[2] = fmaf(-ie2, c.z, h.z);
        tp[3] = fmaf(-ie2, c.w, h.w);
        m = fmaxf(m, fmaxf(fmaxf(tp[0], tp[1]), fmaxf(tp[2], tp[3])));
    }

    red[tid] = m;
    __syncthreads();
#pragma unroll
    for (int s = 128; s > 0; s >>= 1) {
        if (tid < s) red[tid] = fmaxf(red[tid], red[tid + s]);
        __syncthreads();
    }
    float mall = red[0];
    __syncthreads();

    float ssum = 0.0f;
#pragma unroll
    for (int i = 0; i < 16; i++) ssum += exp2f(t[i] - mall);

    red[tid] = ssum;
    __syncthreads();
#pragma unroll
    for (int s = 128; s > 0; s >>= 1) {
        if (tid < s) red[tid] += red[tid + s];
        __syncthreads();
    }

    if (tid == 0) {
        float ft = negEpsLn2 * (mall + log2f(red[0]));
        if (mode == 0)      g_pot[bufout][w][row] = ft;
        else if (mode == 1) g_pot[bufout][w][row] = 0.5f * (g_pot[bufin][w][row] + ft);
        else                g_fin[w][row] = ft;
    }
}

// ---------------------------------------------------------------------------
// Final reduction: (1/N) * sum_i [ (f_ba_n - f_aa_n) + (g_ab_n - g_bb_n) ]
// ---------------------------------------------------------------------------
__global__ void reduce_k(float* __restrict__ out) {
    __shared__ float red[256];
    int tid = threadIdx.x;
    float s = 0.0f;
    for (int j = tid; j < NPTS; j += 256)
        s += (g_fin[0][j] - g_fin[2][j]) + (g_fin[1][j] - g_fin[3][j]);
    red[tid] = s;
    __syncthreads();
#pragma unroll
    for (int k = 128; k > 0; k >>= 1) {
        if (tid < k) red[tid] += red[tid + k];
        __syncthreads();
    }
    if (tid == 0) out[0] = red[0] * (1.0f / (float)NPTS);
}

// ---------------------------------------------------------------------------
extern "C" void kernel_launch(void* const* d_in, const int* in_sizes, int n_in,
                              void* d_out, int out_size) {
    const float* x = (const float*)d_in[0];
    const float* y = (const float*)d_in[1];
    float* out = (float*)d_out;

    // eps schedule: [diam^p] + exp(arange(p*log(diam), p*log(blur), p*log(scaling))) + [blur^p]
    double eps_list[40];
    int ne = 0;
    eps_list[ne++] = 400.0;  // 20^2
    {
        double start = 2.0 * log(20.0);
        double stop  = 2.0 * log(0.01);
        double step  = 2.0 * log(0.7);
        for (int k = 0;; k++) {
            double v = start + (double)k * step;
            if (!(v > stop)) break;
            eps_list[ne++] = exp(v);
        }
    }
    eps_list[ne++] = 1e-4;  // 0.01^2

    const float log_w = -logf(4096.0f);

    // 1. norms
    norms_k<<<(2 * NPTS + 255) / 256, 256>>>(x, y);

    // 2. cost matrices
    dim3 gg(64, 64), bb(16, 16);
    cost_k<<<gg, bb>>>(x, y, 0);   // C_xy
    cost_k<<<gg, bb>>>(y, x, 1);   // C_yx
    cost_k<<<gg, bb>>>(x, x, 2);   // C_xx
    cost_k<<<gg, bb>>>(y, y, 3);   // C_yy

    dim3 sg(NPTS, 4);

    // 3. init at eps_list[0], h = log_w (pot = 0)
    {
        float eps = (float)eps_list[0];
        float inv = 1.0f / eps;
        prep_h2_k<<<(4 * NPTS) / 1024, 1024>>>(0, inv, 1, log_w);
        softmin4_k<<<sg, 256>>>(0, 0, -eps * LN2_F, inv * LOG2E_F, 0);
    }

    // 4. annealing loop (double-buffered potentials)
    int cur = 0;
    for (int it = 0; it < ne; it++) {
        float eps = (float)eps_list[it];
        float inv = 1.0f / eps;
        prep_h2_k<<<(4 * NPTS) / 1024, 1024>>>(cur, inv, 0, log_w);
        softmin4_k<<<sg, 256>>>(cur, cur ^ 1, -eps * LN2_F, inv * LOG2E_F, 1);
        cur ^= 1;
    }

    // 5. final extrapolation at eps = blur^p
    {
        float eps = (float)eps_list[ne - 1];
        float inv = 1.0f / eps;
        prep_h2_k<<<(4 * NPTS) / 1024, 1024>>>(cur, inv, 0, log_w);
        softmin4_k<<<sg, 256>>>(cur, 0, -eps * LN2_F, inv * LOG2E_F, 2);
    }

    // 6. reduce to scalar
    reduce_k<<<1, 256>>>(out);
}

// round 6
// speedup vs baseline: 1.0123x; 1.0123x over previous
#include <cuda_runtime.h>
#include <math.h>

#define NPTS 4096
#define DIM  64
#define LOG2E_F 1.4426950408889634f
#define LN2_F   0.6931471805599453f
#define LW2     (-12.0f)   /* log2(1/4096) = (-ln 4096) * log2(e) */

// Cost matrices: 0 = C_xy, 1 = C_xx, 2 = C_yy   (3 x 64 MB)  — C_yx = C_xy^T, never stored
__device__ float g_C[3][(size_t)NPTS * NPTS];
__device__ float g_n2[2][NPTS];          // squared norms of x, y
__device__ float g_pot[2][4][NPTS];      // double-buffered potentials: f_ba, g_ab, f_aa, g_bb
__device__ float g_fin[4][NPTS];         // final softmin outputs
__device__ float g_rm[16][NPTS], g_rs[16][NPTS];   // row-LSE partials (16 col stripes)
__device__ float g_cm[32][NPTS], g_cs[32][NPTS];   // col-LSE partials (32 row chunks)

// ---------------------------------------------------------------------------
// Squared norms
// ---------------------------------------------------------------------------
__global__ void norms_k(const float* __restrict__ x, const float* __restrict__ y) {
    int i = blockIdx.x * blockDim.x + threadIdx.x;
    if (i >= 2 * NPTS) return;
    const float* p = (i < NPTS) ? (x + (size_t)i * DIM) : (y + (size_t)(i - NPTS) * DIM);
    float s = 0.0f;
#pragma unroll
    for (int k = 0; k < DIM; k += 4) {
        float4 v = *(const float4*)&p[k];
        s += v.x * v.x + v.y * v.y + v.z * v.z + v.w * v.w;
    }
    g_n2[i >= NPTS ? 1 : 0][i & (NPTS - 1)] = s;
}

// ---------------------------------------------------------------------------
// Cost matrix: C[i][j] = 0.5*(|a_i|^2 + |b_j|^2) - a_i . b_j
// sel: 0 = C_xy(x,y), 1 = C_xx(x,x), 2 = C_yy(y,y)
// ---------------------------------------------------------------------------
__global__ __launch_bounds__(256) void cost_k(const float* __restrict__ A,
                                              const float* __restrict__ B,
                                              int sel) {
    __shared__ float As[64][68];
    __shared__ float Bs[64][68];

    int r0 = blockIdx.y * 64, c0 = blockIdx.x * 64;
    int tid = threadIdx.y * 16 + threadIdx.x;

#pragma unroll
    for (int p = 0; p < 4; p++) {
        int q  = tid + p * 256;
        int r  = q >> 4;
        int kc = (q & 15) << 2;
        float4 va = *(const float4*)&A[(size_t)(r0 + r) * DIM + kc];
        As[kc + 0][r] = va.x; As[kc + 1][r] = va.y;
        As[kc + 2][r] = va.z; As[kc + 3][r] = va.w;
        float4 vb = *(const float4*)&B[(size_t)(c0 + r) * DIM + kc];
        Bs[kc + 0][r] = vb.x; Bs[kc + 1][r] = vb.y;
        Bs[kc + 2][r] = vb.z; Bs[kc + 3][r] = vb.w;
    }
    __syncthreads();

    float acc[4][4] = {};
    int ty4 = threadIdx.y * 4, tx4 = threadIdx.x * 4;
#pragma unroll 8
    for (int k = 0; k < 64; k++) {
        float4 a = *(const float4*)&As[k][ty4];
        float4 b = *(const float4*)&Bs[k][tx4];
        acc[0][0] += a.x * b.x; acc[0][1] += a.x * b.y; acc[0][2] += a.x * b.z; acc[0][3] += a.x * b.w;
        acc[1][0] += a.y * b.x; acc[1][1] += a.y * b.y; acc[1][2] += a.y * b.z; acc[1][3] += a.y * b.w;
        acc[2][0] += a.z * b.x; acc[2][1] += a.z * b.y; acc[2][2] += a.z * b.z; acc[2][3] += a.z * b.w;
        acc[3][0] += a.w * b.x; acc[3][1] += a.w * b.y; acc[3][2] += a.w * b.z; acc[3][3] += a.w * b.w;
    }

    const float* na = (sel == 2) ? g_n2[1] : g_n2[0];
    const float* nb = (sel == 1) ? g_n2[0] : g_n2[1];
    float* Cout = g_C[sel];

    float nbv[4];
#pragma unroll
    for (int jj = 0; jj < 4; jj++) nbv[jj] = 0.5f * nb[c0 + tx4 + jj];
#pragma unroll
    for (int ii = 0; ii < 4; ii++) {
        int i = r0 + ty4 + ii;
        float ni = 0.5f * na[i];
        float4 o;
        o.x = ni + nbv[0] - acc[ii][0];
        o.y = ni + nbv[1] - acc[ii][1];
        o.z = ni + nbv[2] - acc[ii][2];
        o.w = ni + nbv[3] - acc[ii][3];
        *(float4*)&Cout[(size_t)i * NPTS + c0 + tx4] = o;
    }
}

// ---------------------------------------------------------------------------
// Single streaming kernel per iteration. Grid = 512 + 8192 blocks, 256 threads.
//   blocks [0,512):      fused row+col LSE over C_xy (16 col-stripes x 32 row-chunks,
//                        tile 128 rows x 256 cols). Writes partials g_rm/rs, g_cm/cs.
//   blocks [512, 8704):  block-per-row LSE over C_xx / C_yy (symmetric: row==col),
//                        writes f_aa / g_bb potentials directly.
// mode: 0 = init (h = log_w, raw write), 1 = loop (averaged), 2 = final (write g_fin)
// All math in log2 domain: t = h2 - C*ie2, h2 = fma(pot, ie2, LW2).
// ---------------------------------------------------------------------------
__global__ __launch_bounds__(256) void big_k(int cur, int nxt,
                                             float negEpsLn2, float ie2, int mode) {
    __shared__ float smm[8][256];
    __shared__ float sms[8][256];
    int b = blockIdx.x, tid = threadIdx.x;

    if (b < 512) {
        // ------------------ fused C_xy pass ------------------
        int bx = b & 15, by = b >> 4;
        int c0 = bx << 8, r0 = by << 7;
        int lane = tid & 31, wp = tid >> 5;

        const float* pota = g_pot[cur][0];   // f_ba -> h for col direction (g update)
        const float* potb = g_pot[cur][1];   // g_ab -> h for row direction (f update)

        float hb[8];
        if (mode == 0) {
#pragma unroll
            for (int i = 0; i < 8; i++) hb[i] = LW2;
        } else {
            float4 p0 = *(const float4*)&potb[c0 + 8 * lane];
            float4 p1 = *(const float4*)&potb[c0 + 8 * lane + 4];
            hb[0] = fmaf(p0.x, ie2, LW2); hb[1] = fmaf(p0.y, ie2, LW2);
            hb[2] = fmaf(p0.z, ie2, LW2); hb[3] = fmaf(p0.w, ie2, LW2);
            hb[4] = fmaf(p1.x, ie2, LW2); hb[5] = fmaf(p1.y, ie2, LW2);
            hb[6] = fmaf(p1.z, ie2, LW2); hb[7] = fmaf(p1.w, ie2, LW2);
        }

        float mc[8], sc[8];
#pragma unroll
        for (int i = 0; i < 8; i++) { mc[i] = -3.3e38f; sc[i] = 0.0f; }

#pragma unroll 2
        for (int k = 0; k < 16; k++) {
            int r = r0 + wp + (k << 3);
            float ha = (mode == 0) ? LW2 : fmaf(pota[r], ie2, LW2);

            const float4* C4 = (const float4*)(g_C[0] + (size_t)r * NPTS + c0 + 8 * lane);
            float4 ca = C4[0], cb = C4[1];
            float u[8];
            u[0] = ca.x * ie2; u[1] = ca.y * ie2; u[2] = ca.z * ie2; u[3] = ca.w * ie2;
            u[4] = cb.x * ie2; u[5] = cb.y * ie2; u[6] = cb.z * ie2; u[7] = cb.w * ie2;

            // row direction (f update): local 8-wide LSE then warp merge
            float tf[8], ml = -3.3e38f;
#pragma unroll
            for (int i = 0; i < 8; i++) { tf[i] = hb[i] - u[i]; ml = fmaxf(ml, tf[i]); }
            float sl = 0.0f;
#pragma unroll
            for (int i = 0; i < 8; i++) sl += exp2f(tf[i] - ml);
#pragma unroll
            for (int off = 16; off; off >>= 1) {
                float mo = __shfl_xor_sync(0xFFFFFFFFu, ml, off);
                float so = __shfl_xor_sync(0xFFFFFFFFu, sl, off);
                float d = mo - ml;
                float e = exp2f(-fabsf(d));
                if (d > 0.0f) { sl = fmaf(sl, e, so); ml = mo; }
                else          { sl = fmaf(so, e, sl); }
            }
            if (lane == 0) { g_rm[bx][r] = ml; g_rs[bx][r] = sl; }

            // col direction (g update): thread-local online LSE per column
#pragma unroll
            for (int i = 0; i < 8; i++) {
                float tg = ha - u[i];
                float d = tg - mc[i];
                float e = exp2f(-fabsf(d));
                if (d > 0.0f) { sc[i] = fmaf(sc[i], e, 1.0f); mc[i] = tg; }
                else          { sc[i] += e; }
            }
        }

        // in-block merge of 8 warp col-partials per column
#pragma unroll
        for (int i = 0; i < 8; i++) {
            smm[wp][lane * 8 + i] = mc[i];
            sms[wp][lane * 8 + i] = sc[i];
        }
        __syncthreads();
        float mm = smm[0][tid], ssv = sms[0][tid];
#pragma unroll
        for (int w = 1; w < 8; w++) {
            float mo = smm[w][tid], so = sms[w][tid];
            float d = mo - mm;
            float e = exp2f(-fabsf(d));
            if (d > 0.0f) { ssv = fmaf(ssv, e, so); mm = mo; }
            else          { ssv = fmaf(so, e, ssv); }
        }
        g_cm[by][c0 + tid] = mm;
        g_cs[by][c0 + tid] = ssv;
    } else {
        // ------------------ symmetric C_xx / C_yy row pass ------------------
        b -= 512;
        int w = b >> 12, row = b & (NPTS - 1);   // w: 0 = xx (f_aa), 1 = yy (g_bb)
        const float4* C4 = (const float4*)(g_C[1 + w] + (size_t)row * NPTS);
        const float4* P4 = (const float4*)(g_pot[cur][2 + w]);

        float t[16];
        float m = -3.3e38f;
#pragma unroll
        for (int p = 0; p < 4; p++) {
            int q = tid + p * 256;
            float4 c = C4[q];
            float hx, hy, hz, hw;
            if (mode == 0) { hx = hy = hz = hw = LW2; }
            else {
                float4 pv = P4[q];
                hx = fmaf(pv.x, ie2, LW2); hy = fmaf(pv.y, ie2, LW2);
                hz = fmaf(pv.z, ie2, LW2); hw = fmaf(pv.w, ie2, LW2);
            }
            float* tp = &t[p * 4];
            tp[0] = fmaf(-ie2, c.x, hx);
            tp[1] = fmaf(-ie2, c.y, hy);
            tp[2] = fmaf(-ie2, c.z, hz);
            tp[3] = fmaf(-ie2, c.w, hw);
            m = fmaxf(m, fmaxf(fmaxf(tp[0], tp[1]), fmaxf(tp[2], tp[3])));
        }

        float* red = &smm[0][0];
        red[tid] = m;
        __syncthreads();
#pragma unroll
        for (int s = 128; s > 0; s >>= 1) {
            if (tid < s) red[tid] = fmaxf(red[tid], red[tid + s]);
            __syncthreads();
        }
        float mall = red[0];
        __syncthreads();

        float ssum = 0.0f;
#pragma unroll
        for (int i = 0; i < 16; i++) ssum += exp2f(t[i] - mall);
        red[tid] = ssum;
        __syncthreads();
#pragma unroll
        for (int s = 128; s > 0; s >>= 1) {
            if (tid < s) red[tid] += red[tid + s];
            __syncthreads();
        }

        if (tid == 0) {
            float ft = negEpsLn2 * (mall + log2f(red[0]));
            if (mode == 0)      g_pot[nxt][2 + w][row] = ft;
            else if (mode == 1) g_pot[nxt][2 + w][row] = 0.5f * (g_pot[cur][2 + w][row] + ft);
            else                g_fin[2 + w][row] = ft;
        }
    }
}

// ---------------------------------------------------------------------------
// Merge partials: rows (16 stripes) -> f_ba update; cols (32 chunks) -> g_ab.
// Grid 32 x 256 = 8192 threads.
// ---------------------------------------------------------------------------
__global__ void merge_k(int cur, int nxt, float negEpsLn2, int mode) {
    int g = blockIdx.x * blockDim.x + threadIdx.x;
    if (g < NPTS) {
        int r = g;
        float m = g_rm[0][r], s = g_rs[0][r];
#pragma unroll
        for (int k = 1; k < 16; k++) {
            float mo = g_rm[k][r], so = g_rs[k][r];
            float d = mo - m;
            float e = exp2f(-fabsf(d));
            if (d > 0.0f) { s = fmaf(s, e, so); m = mo; }
            else          { s = fmaf(so, e, s); }
        }
        float ft = negEpsLn2 * (m + log2f(s));
        if (mode == 0)      g_pot[nxt][0][r] = ft;
        else if (mode == 1) g_pot[nxt][0][r] = 0.5f * (g_pot[cur][0][r] + ft);
        else                g_fin[0][r] = ft;
    } else {
        int c = g - NPTS;
        float m = g_cm[0][c], s = g_cs[0][c];
#pragma unroll
        for (int k = 1; k < 32; k++) {
            float mo = g_cm[k][c], so = g_cs[k][c];
            float d = mo - m;
            float e = exp2f(-fabsf(d));
            if (d > 0.0f) { s = fmaf(s, e, so); m = mo; }
            else          { s = fmaf(so, e, s); }
        }
        float gt = negEpsLn2 * (m + log2f(s));
        if (mode == 0)      g_pot[nxt][1][c] = gt;
        else if (mode == 1) g_pot[nxt][1][c] = 0.5f * (g_pot[cur][1][c] + gt);
        else                g_fin[1][c] = gt;
    }
}

// ---------------------------------------------------------------------------
// Final reduction: (1/N) * sum_i [ (f_ba_n - f_aa_n) + (g_ab_n - g_bb_n) ]
// ---------------------------------------------------------------------------
__global__ void reduce_k(float* __restrict__ out) {
    __shared__ float red[256];
    int tid = threadIdx.x;
    float s = 0.0f;
    for (int j = tid; j < NPTS; j += 256)
        s += (g_fin[0][j] - g_fin[2][j]) + (g_fin[1][j] - g_fin[3][j]);
    red[tid] = s;
    __syncthreads();
#pragma unroll
    for (int k = 128; k > 0; k >>= 1) {
        if (tid < k) red[tid] += red[tid + k];
        __syncthreads();
    }
    if (tid == 0) out[0] = red[0] * (1.0f / (float)NPTS);
}

// ---------------------------------------------------------------------------
extern "C" void kernel_launch(void* const* d_in, const int* in_sizes, int n_in,
                              void* d_out, int out_size) {
    const float* x = (const float*)d_in[0];
    const float* y = (const float*)d_in[1];
    float* out = (float*)d_out;

    // eps schedule
    double eps_list[40];
    int ne = 0;
    eps_list[ne++] = 400.0;
    {
        double start = 2.0 * log(20.0);
        double stop  = 2.0 * log(0.01);
        double step  = 2.0 * log(0.7);
        for (int k = 0;; k++) {
            double v = start + (double)k * step;
            if (!(v > stop)) break;
            eps_list[ne++] = exp(v);
        }
    }
    eps_list[ne++] = 1e-4;

    const int NB = 512 + 2 * NPTS;   // big_k grid

    // 1. norms + cost matrices (C_yx never built)
    norms_k<<<(2 * NPTS + 255) / 256, 256>>>(x, y);
    dim3 gg(64, 64), bb(16, 16);
    cost_k<<<gg, bb>>>(x, y, 0);   // C_xy
    cost_k<<<gg, bb>>>(x, x, 1);   // C_xx
    cost_k<<<gg, bb>>>(y, y, 2);   // C_yy

    // 2. init at eps_list[0] (h = log_w)
    {
        float eps = (float)eps_list[0];
        float ie2 = (1.0f / eps) * LOG2E_F;
        big_k<<<NB, 256>>>(0, 0, -eps * LN2_F, ie2, 0);
        merge_k<<<32, 256>>>(0, 0, -eps * LN2_F, 0);
    }

    // 3. annealing loop
    int cur = 0;
    for (int it = 0; it < ne; it++) {
        float eps = (float)eps_list[it];
        float ie2 = (1.0f / eps) * LOG2E_F;
        big_k<<<NB, 256>>>(cur, cur ^ 1, -eps * LN2_F, ie2, 1);
        merge_k<<<32, 256>>>(cur, cur ^ 1, -eps * LN2_F, 1);
        cur ^= 1;
    }

    // 4. final extrapolation at eps = blur^p
    {
        float eps = (float)eps_list[ne - 1];
        float ie2 = (1.0f / eps) * LOG2E_F;
        big_k<<<NB, 256>>>(cur, 0, -eps * LN2_F, ie2, 2);
        merge_k<<<32, 256>>>(cur, 0, -eps * LN2_F, 2);
    }

    // 5. reduce to scalar
    reduce_k<<<1, 256>>>(out);
}

// round 9
// speedup vs baseline: 1.1173x; 1.1037x over previous
#include <cuda_runtime.h>
#include <math.h>

#define NPTS 4096
#define DIM  64
#define LOG2E_F 1.4426950408889634f
#define LN2_F   0.6931471805599453f
#define LW2     (-12.0f)   /* log2(1/4096) */

// Cost matrices: 0 = C_xy, 1 = C_xx, 2 = C_yy  (C_yx = C_xy^T, never stored)
__device__ float g_C[3][(size_t)NPTS * NPTS];
__device__ float g_n2[2][NPTS];
__device__ float g_pot[2][4][NPTS];      // double-buffered: f_ba, g_ab, f_aa, g_bb
__device__ float g_fin[4][NPTS];
__device__ float g_rm[16][NPTS], g_rs[16][NPTS];     // xy row-LSE partials (16 col stripes)
__device__ float g_cm[128][NPTS], g_cs[128][NPTS];   // xy col-LSE partials (128 row chunks)

// ---------------------------------------------------------------------------
__global__ void norms_k(const float* __restrict__ x, const float* __restrict__ y) {
    int i = blockIdx.x * blockDim.x + threadIdx.x;
    if (i >= 2 * NPTS) return;
    const float* p = (i < NPTS) ? (x + (size_t)i * DIM) : (y + (size_t)(i - NPTS) * DIM);
    float s = 0.0f;
#pragma unroll
    for (int k = 0; k < DIM; k += 4) {
        float4 v = *(const float4*)&p[k];
        s += v.x * v.x + v.y * v.y + v.z * v.z + v.w * v.w;
    }
    g_n2[i >= NPTS ? 1 : 0][i & (NPTS - 1)] = s;
}

// ---------------------------------------------------------------------------
// Cost matrix: C[i][j] = 0.5*(|a_i|^2 + |b_j|^2) - a_i . b_j
// sel: 0 = C_xy(x,y), 1 = C_xx(x,x), 2 = C_yy(y,y)
// ---------------------------------------------------------------------------
__global__ __launch_bounds__(256) void cost_k(const float* __restrict__ A,
                                              const float* __restrict__ B,
                                              int sel) {
    __shared__ float As[64][68];
    __shared__ float Bs[64][68];

    int r0 = blockIdx.y * 64, c0 = blockIdx.x * 64;
    int tid = threadIdx.y * 16 + threadIdx.x;

#pragma unroll
    for (int p = 0; p < 4; p++) {
        int q  = tid + p * 256;
        int r  = q >> 4;
        int kc = (q & 15) << 2;
        float4 va = *(const float4*)&A[(size_t)(r0 + r) * DIM + kc];
        As[kc + 0][r] = va.x; As[kc + 1][r] = va.y;
        As[kc + 2][r] = va.z; As[kc + 3][r] = va.w;
        float4 vb = *(const float4*)&B[(size_t)(c0 + r) * DIM + kc];
        Bs[kc + 0][r] = vb.x; Bs[kc + 1][r] = vb.y;
        Bs[kc + 2][r] = vb.z; Bs[kc + 3][r] = vb.w;
    }
    __syncthreads();

    float acc[4][4] = {};
    int ty4 = threadIdx.y * 4, tx4 = threadIdx.x * 4;
#pragma unroll 8
    for (int k = 0; k < 64; k++) {
        float4 a = *(const float4*)&As[k][ty4];
        float4 b = *(const float4*)&Bs[k][tx4];
        acc[0][0] += a.x * b.x; acc[0][1] += a.x * b.y; acc[0][2] += a.x * b.z; acc[0][3] += a.x * b.w;
        acc[1][0] += a.y * b.x; acc[1][1] += a.y * b.y; acc[1][2] += a.y * b.z; acc[1][3] += a.y * b.w;
        acc[2][0] += a.z * b.x; acc[2][1] += a.z * b.y; acc[2][2] += a.z * b.z; acc[2][3] += a.z * b.w;
        acc[3][0] += a.w * b.x; acc[3][1] += a.w * b.y; acc[3][2] += a.w * b.z; acc[3][3] += a.w * b.w;
    }

    const float* na = (sel == 2) ? g_n2[1] : g_n2[0];
    const float* nb = (sel == 1) ? g_n2[0] : g_n2[1];
    float* Cout = g_C[sel];

    float nbv[4];
#pragma unroll
    for (int jj = 0; jj < 4; jj++) nbv[jj] = 0.5f * nb[c0 + tx4 + jj];
#pragma unroll
    for (int ii = 0; ii < 4; ii++) {
        int i = r0 + ty4 + ii;
        float ni = 0.5f * na[i];
        float4 o;
        o.x = ni + nbv[0] - acc[ii][0];
        o.y = ni + nbv[1] - acc[ii][1];
        o.z = ni + nbv[2] - acc[ii][2];
        o.w = ni + nbv[3] - acc[ii][3];
        *(float4*)&Cout[(size_t)i * NPTS + c0 + tx4] = o;
    }
}

// online LSE state update (log2 domain): state (m,s) += value t
__device__ __forceinline__ void lse_upd(float& m, float& s, float t) {
    float d = t - m;
    float e = exp2f(-fabsf(d));
    if (d > 0.0f) { s = fmaf(s, e, 1.0f); m = t; }
    else          { s += e; }
}
// merge state (mo,so) into (m,s)
__device__ __forceinline__ void lse_mrg(float& m, float& s, float mo, float so) {
    float d = mo - m;
    float e = exp2f(-fabsf(d));
    if (d > 0.0f) { s = fmaf(s, e, so); m = mo; }
    else          { s = fmaf(so, e, s); }
}

// ---------------------------------------------------------------------------
// One streaming kernel per iteration. Grid = 1024 + 2048 blocks, 256 threads.
//   blocks [0,1024):     xx/yy: warp-per-row (8 warps/blk -> 8192 rows), barrier-free
//                        online LSE, writes f_aa / g_bb potentials directly.
//   blocks [1024,3072):  fused row+col LSE over C_xy. Tile 32 rows x 256 cols,
//                        16 col-stripes x 128 row-chunks. Row dir: per-row warp
//                        shuffle LSE -> g_rm/g_rs. Col dir: 8 thread-local online
//                        states + one smem merge -> g_cm/g_cs.
// mode: 0 = init (h = log_w), 1 = loop (averaged), 2 = final (write g_fin)
// ---------------------------------------------------------------------------
__global__ __launch_bounds__(256) void big_k(int cur, int nxt,
                                             float negEpsLn2, float ie2, int mode) {
    __shared__ float smm[8][256];
    __shared__ float sms[8][256];
    int b = blockIdx.x, tid = threadIdx.x;
    int lane = tid & 31, wp = tid >> 5;

    if (b < 1024) {
        // ---------------- xx / yy : warp-per-row ----------------
        int gr = b * 8 + wp;            // 0..8191
        int w = gr >> 12;               // 0 = xx (f_aa), 1 = yy (g_bb)
        int row = gr & (NPTS - 1);
        const float4* C4 = (const float4*)(g_C[1 + w] + (size_t)row * NPTS);
        const float4* P4 = (const float4*)(g_pot[cur][2 + w]);

        float m0 = -3.3e38f, m1 = -3.3e38f, m2 = -3.3e38f, m3 = -3.3e38f;
        float s0 = 0.0f, s1 = 0.0f, s2 = 0.0f, s3 = 0.0f;

#pragma unroll 4
        for (int it = 0; it < 32; it++) {
            int q = lane + it * 32;
            float4 c = C4[q];
            float tx, ty, tz, tw;
            if (mode == 0) {
                tx = fmaf(-ie2, c.x, LW2); ty = fmaf(-ie2, c.y, LW2);
                tz = fmaf(-ie2, c.z, LW2); tw = fmaf(-ie2, c.w, LW2);
            } else {
                float4 pv = P4[q];
                tx = fmaf(-ie2, c.x, fmaf(pv.x, ie2, LW2));
                ty = fmaf(-ie2, c.y, fmaf(pv.y, ie2, LW2));
                tz = fmaf(-ie2, c.z, fmaf(pv.z, ie2, LW2));
                tw = fmaf(-ie2, c.w, fmaf(pv.w, ie2, LW2));
            }
            lse_upd(m0, s0, tx); lse_upd(m1, s1, ty);
            lse_upd(m2, s2, tz); lse_upd(m3, s3, tw);
        }
        lse_mrg(m0, s0, m1, s1);
        lse_mrg(m2, s2, m3, s3);
        lse_mrg(m0, s0, m2, s2);
#pragma unroll
        for (int off = 16; off; off >>= 1) {
            float mo = __shfl_xor_sync(0xFFFFFFFFu, m0, off);
            float so = __shfl_xor_sync(0xFFFFFFFFu, s0, off);
            lse_mrg(m0, s0, mo, so);
        }
        if (lane == 0) {
            float ft = negEpsLn2 * (m0 + log2f(s0));
            if (mode == 0)      g_pot[nxt][2 + w][row] = ft;
            else if (mode == 1) g_pot[nxt][2 + w][row] = 0.5f * (g_pot[cur][2 + w][row] + ft);
            else                g_fin[2 + w][row] = ft;
        }
    } else {
        // ---------------- fused C_xy pass ----------------
        b -= 1024;
        int bx = b & 15, by = b >> 4;
        int c0 = bx << 8, r0 = by << 5;     // 256 cols, 32 rows

        const float* pota = g_pot[cur][0];  // f_ba -> h for col direction
        const float* potb = g_pot[cur][1];  // g_ab -> h for row direction

        int j0 = 4 * lane, j1 = 128 + 4 * lane;

        float hb[8];
        if (mode == 0) {
#pragma unroll
            for (int i = 0; i < 8; i++) hb[i] = LW2;
        } else {
            float4 p0 = *(const float4*)&potb[c0 + j0];
            float4 p1 = *(const float4*)&potb[c0 + j1];
            hb[0] = fmaf(p0.x, ie2, LW2); hb[1] = fmaf(p0.y, ie2, LW2);
            hb[2] = fmaf(p0.z, ie2, LW2); hb[3] = fmaf(p0.w, ie2, LW2);
            hb[4] = fmaf(p1.x, ie2, LW2); hb[5] = fmaf(p1.y, ie2, LW2);
            hb[6] = fmaf(p1.z, ie2, LW2); hb[7] = fmaf(p1.w, ie2, LW2);
        }

        float mc[8], sc[8];
#pragma unroll
        for (int i = 0; i < 8; i++) { mc[i] = -3.3e38f; sc[i] = 0.0f; }

#pragma unroll
        for (int g = 0; g < 4; g++) {
            int r = r0 + g * 8 + wp;
            float ha = (mode == 0) ? LW2 : fmaf(pota[r], ie2, LW2);

            const float* Crow = g_C[0] + (size_t)r * NPTS + c0;
            float4 ca = *(const float4*)&Crow[j0];
            float4 cb = *(const float4*)&Crow[j1];
            float u[8];
            u[0] = ca.x * ie2; u[1] = ca.y * ie2; u[2] = ca.z * ie2; u[3] = ca.w * ie2;
            u[4] = cb.x * ie2; u[5] = cb.y * ie2; u[6] = cb.z * ie2; u[7] = cb.w * ie2;

            // row direction: warp max, then 1 exp/elem, warp sum
            float t[8], ml = -3.3e38f;
#pragma unroll
            for (int i = 0; i < 8; i++) { t[i] = hb[i] - u[i]; ml = fmaxf(ml, t[i]); }
#pragma unroll
            for (int off = 16; off; off >>= 1)
                ml = fmaxf(ml, __shfl_xor_sync(0xFFFFFFFFu, ml, off));
            float sl = 0.0f;
#pragma unroll
            for (int i = 0; i < 8; i++) sl += exp2f(t[i] - ml);
#pragma unroll
            for (int off = 16; off; off >>= 1)
                sl += __shfl_xor_sync(0xFFFFFFFFu, sl, off);
            if (lane == 0) { g_rm[bx][r] = ml; g_rs[bx][r] = sl; }

            // col direction: thread-local online LSE per fixed column
#pragma unroll
            for (int i = 0; i < 8; i++) lse_upd(mc[i], sc[i], ha - u[i]);
        }

        // merge 8 warps' col partials (warp w saw rows g*8+w)
#pragma unroll
        for (int i = 0; i < 4; i++) {
            smm[wp][j0 + i] = mc[i];     sms[wp][j0 + i] = sc[i];
            smm[wp][j1 + i] = mc[4 + i]; sms[wp][j1 + i] = sc[4 + i];
        }
        __syncthreads();
        float mm = smm[0][tid], ssv = sms[0][tid];
#pragma unroll
        for (int w = 1; w < 8; w++) lse_mrg(mm, ssv, smm[w][tid], sms[w][tid]);
        g_cm[by][c0 + tid] = mm;
        g_cs[by][c0 + tid] = ssv;
    }
}

// ---------------------------------------------------------------------------
// Merge xy partials: rows (16 stripes) -> f_ba; cols (128 chunks) -> g_ab.
// ---------------------------------------------------------------------------
__global__ void merge_k(int cur, int nxt, float negEpsLn2, int mode) {
    int g = blockIdx.x * blockDim.x + threadIdx.x;
    if (g < NPTS) {
        int r = g;
        float m = g_rm[0][r], s = g_rs[0][r];
#pragma unroll
        for (int k = 1; k < 16; k++) lse_mrg(m, s, g_rm[k][r], g_rs[k][r]);
        float ft = negEpsLn2 * (m + log2f(s));
        if (mode == 0)      g_pot[nxt][0][r] = ft;
        else if (mode == 1) g_pot[nxt][0][r] = 0.5f * (g_pot[cur][0][r] + ft);
        else                g_fin[0][r] = ft;
    } else {
        int c = g - NPTS;
        float m = g_cm[0][c], s = g_cs[0][c];
#pragma unroll 16
        for (int k = 1; k < 128; k++) lse_mrg(m, s, g_cm[k][c], g_cs[k][c]);
        float gt = negEpsLn2 * (m + log2f(s));
        if (mode == 0)      g_pot[nxt][1][c] = gt;
        else if (mode == 1) g_pot[nxt][1][c] = 0.5f * (g_pot[cur][1][c] + gt);
        else                g_fin[1][c] = gt;
    }
}

// ---------------------------------------------------------------------------
__global__ void reduce_k(float* __restrict__ out) {
    __shared__ float red[256];
    int tid = threadIdx.x;
    float s = 0.0f;
    for (int j = tid; j < NPTS; j += 256)
        s += (g_fin[0][j] - g_fin[2][j]) + (g_fin[1][j] - g_fin[3][j]);
    red[tid] = s;
    __syncthreads();
#pragma unroll
    for (int k = 128; k > 0; k >>= 1) {
        if (tid < k) red[tid] += red[tid + k];
        __syncthreads();
    }
    if (tid == 0) out[0] = red[0] * (1.0f / (float)NPTS);
}

// ---------------------------------------------------------------------------
extern "C" void kernel_launch(void* const* d_in, const int* in_sizes, int n_in,
                              void* d_out, int out_size) {
    const float* x = (const float*)d_in[0];
    const float* y = (const float*)d_in[1];
    float* out = (float*)d_out;

    double eps_list[40];
    int ne = 0;
    eps_list[ne++] = 400.0;
    {
        double start = 2.0 * log(20.0);
        double stop  = 2.0 * log(0.01);
        double step  = 2.0 * log(0.7);
        for (int k = 0;; k++) {
            double v = start + (double)k * step;
            if (!(v > stop)) break;
            eps_list[ne++] = exp(v);
        }
    }
    eps_list[ne++] = 1e-4;

    const int NB = 1024 + 2048;

    norms_k<<<(2 * NPTS + 255) / 256, 256>>>(x, y);
    dim3 gg(64, 64), bb(16, 16);
    cost_k<<<gg, bb>>>(x, y, 0);   // C_xy
    cost_k<<<gg, bb>>>(x, x, 1);   // C_xx
    cost_k<<<gg, bb>>>(y, y, 2);   // C_yy

    // init at eps_list[0] (h = log_w)
    {
        float eps = (float)eps_list[0];
        float ie2 = (1.0f / eps) * LOG2E_F;
        big_k<<<NB, 256>>>(0, 0, -eps * LN2_F, ie2, 0);
        merge_k<<<32, 256>>>(0, 0, -eps * LN2_F, 0);
    }

    // annealing loop
    int cur = 0;
    for (int it = 0; it < ne; it++) {
        float eps = (float)eps_list[it];
        float ie2 = (1.0f / eps) * LOG2E_F;
        big_k<<<NB, 256>>>(cur, cur ^ 1, -eps * LN2_F, ie2, 1);
        merge_k<<<32, 256>>>(cur, cur ^ 1, -eps * LN2_F, 1);
        cur ^= 1;
    }

    // final extrapolation at eps = blur^p
    {
        float eps = (float)eps_list[ne - 1];
        float ie2 = (1.0f / eps) * LOG2E_F;
        big_k<<<NB, 256>>>(cur, 0, -eps * LN2_F, ie2, 2);
        merge_k<<<32, 256>>>(cur, 0, -eps * LN2_F, 2);
    }

    reduce_k<<<1, 256>>>(out);
}

// round 12
// speedup vs baseline: 1.2575x; 1.1255x over previous
#include <cuda_runtime.h>
#include <math.h>

#define NPTS 4096
#define DIM  64
#define LOG2E_F 1.4426950408889634f
#define LN2_F   0.6931471805599453f
#define LW2     (-12.0f)   /* log2(1/4096) */
#define SENT    (-3.3e38f)

// Cost matrices: 0 = C_xy, 1 = C_xx, 2 = C_yy  (C_yx = C_xy^T; xx/yy read as triangles)
__device__ float g_C[3][(size_t)NPTS * NPTS];
__device__ float g_n2[2][NPTS];
__device__ float g_pot[2][4][NPTS];      // double-buffered: f_ba, g_ab, f_aa, g_bb
__device__ float g_fin[4][NPTS];
// LSE partials per matrix: row-dir slots [16] (by 256-col chunk J), col-dir slots [32] (by 128-row chunk I)
__device__ float g_Rm[3][16][NPTS], g_Rs[3][16][NPTS];
__device__ float g_Km[3][32][NPTS], g_Ks[3][32][NPTS];

// ---------------------------------------------------------------------------
__global__ void norms_k(const float* __restrict__ x, const float* __restrict__ y) {
    int i = blockIdx.x * blockDim.x + threadIdx.x;
    if (i >= 2 * NPTS) return;
    const float* p = (i < NPTS) ? (x + (size_t)i * DIM) : (y + (size_t)(i - NPTS) * DIM);
    float s = 0.0f;
#pragma unroll
    for (int k = 0; k < DIM; k += 4) {
        float4 v = *(const float4*)&p[k];
        s += v.x * v.x + v.y * v.y + v.z * v.z + v.w * v.w;
    }
    g_n2[i >= NPTS ? 1 : 0][i & (NPTS - 1)] = s;
}

// ---------------------------------------------------------------------------
// Cost matrix: C[i][j] = 0.5*(|a_i|^2 + |b_j|^2) - a_i . b_j
// sel: 0 = C_xy(x,y), 1 = C_xx(x,x), 2 = C_yy(y,y)
// For sym matrices only the upper 256-chunk block-triangle is ever read.
// ---------------------------------------------------------------------------
__global__ __launch_bounds__(256) void cost_k(const float* __restrict__ A,
                                              const float* __restrict__ B,
                                              int sel) {
    if (sel != 0 && (blockIdx.y >> 2) > (blockIdx.x >> 2)) return;

    __shared__ float As[64][68];
    __shared__ float Bs[64][68];

    int r0 = blockIdx.y * 64, c0 = blockIdx.x * 64;
    int tid = threadIdx.y * 16 + threadIdx.x;

#pragma unroll
    for (int p = 0; p < 4; p++) {
        int q  = tid + p * 256;
        int r  = q >> 4;
        int kc = (q & 15) << 2;
        float4 va = *(const float4*)&A[(size_t)(r0 + r) * DIM + kc];
        As[kc + 0][r] = va.x; As[kc + 1][r] = va.y;
        As[kc + 2][r] = va.z; As[kc + 3][r] = va.w;
        float4 vb = *(const float4*)&B[(size_t)(c0 + r) * DIM + kc];
        Bs[kc + 0][r] = vb.x; Bs[kc + 1][r] = vb.y;
        Bs[kc + 2][r] = vb.z; Bs[kc + 3][r] = vb.w;
    }
    __syncthreads();

    float acc[4][4] = {};
    int ty4 = threadIdx.y * 4, tx4 = threadIdx.x * 4;
#pragma unroll 8
    for (int k = 0; k < 64; k++) {
        float4 a = *(const float4*)&As[k][ty4];
        float4 b = *(const float4*)&Bs[k][tx4];
        acc[0][0] += a.x * b.x; acc[0][1] += a.x * b.y; acc[0][2] += a.x * b.z; acc[0][3] += a.x * b.w;
        acc[1][0] += a.y * b.x; acc[1][1] += a.y * b.y; acc[1][2] += a.y * b.z; acc[1][3] += a.y * b.w;
        acc[2][0] += a.z * b.x; acc[2][1] += a.z * b.y; acc[2][2] += a.z * b.z; acc[2][3] += a.z * b.w;
        acc[3][0] += a.w * b.x; acc[3][1] += a.w * b.y; acc[3][2] += a.w * b.z; acc[3][3] += a.w * b.w;
    }

    const float* na = (sel == 2) ? g_n2[1] : g_n2[0];
    const float* nb = (sel == 1) ? g_n2[0] : g_n2[1];
    float* Cout = g_C[sel];

    float nbv[4];
#pragma unroll
    for (int jj = 0; jj < 4; jj++) nbv[jj] = 0.5f * nb[c0 + tx4 + jj];
#pragma unroll
    for (int ii = 0; ii < 4; ii++) {
        int i = r0 + ty4 + ii;
        float ni = 0.5f * na[i];
        float4 o;
        o.x = ni + nbv[0] - acc[ii][0];
        o.y = ni + nbv[1] - acc[ii][1];
        o.z = ni + nbv[2] - acc[ii][2];
        o.w = ni + nbv[3] - acc[ii][3];
        *(float4*)&Cout[(size_t)i * NPTS + c0 + tx4] = o;
    }
}

// online LSE update / merge (log2 domain)
__device__ __forceinline__ void lse_upd(float& m, float& s, float t) {
    float d = t - m;
    float e = exp2f(-fabsf(d));
    if (d > 0.0f) { s = fmaf(s, e, 1.0f); m = t; }
    else          { s += e; }
}
__device__ __forceinline__ void lse_mrg(float& m, float& s, float mo, float so) {
    float d = mo - m;
    float e = exp2f(-fabsf(d));
    if (d > 0.0f) { s = fmaf(s, e, so); m = mo; }
    else          { s = fmaf(so, e, s); }
}

// ---------------------------------------------------------------------------
// Uniform fused tile kernel. Tile = 128 rows x 256 cols. Grid = 1056 blocks:
//   b in [0,512):       xy tiles, I = b&31 (row chunk), J = b>>5 (col chunk)
//   b in [512,784):     xx tiles (I,J) with I <= 2J+1 (triangular enumeration)
//   b in [784,1056):    yy tiles
// Row-dir LSE partial -> g_Rm[mat][J][row]; col-dir -> g_Km[mat][I][col].
// Sym matrices: h_row == h_col == own potential; diag tiles' col partials land
// in slots the merge never reads. mode 0: h = LW2 (init).
// ---------------------------------------------------------------------------
__global__ __launch_bounds__(256) void big_k(int cur, float ie2, int mode) {
    __shared__ float smM[128][33];
    __shared__ float smS[128][33];
    int b = blockIdx.x, tid = threadIdx.x;
    int lane = tid & 31, wp = tid >> 5;

    int mat, I, J;
    const float *hr_pot, *hc_pot;
    if (b < 512) {
        mat = 0; I = b & 31; J = b >> 5;
        hr_pot = g_pot[cur][1];     // g_ab over cols (y)
        hc_pot = g_pot[cur][0];     // f_ba over rows (x)
    } else {
        int t = b - 512;
        int s = (t >= 272) ? 1 : 0;
        t -= 272 * s;
        int Jv = (int)(0.5f * (sqrtf((float)(4 * t + 1)) - 1.0f));
        while (Jv * Jv + Jv > t) Jv--;
        while ((Jv + 1) * (Jv + 1) + (Jv + 1) <= t) Jv++;
        J = Jv; I = t - (Jv * Jv + Jv);        // I in [0, 2J+1]
        mat = 1 + s;
        hr_pot = hc_pot = g_pot[cur][2 + s];
    }
    const float* M = g_C[mat];
    int r0 = I << 7, c0 = J << 8;
    int j0 = 4 * lane, j1 = 128 + 4 * lane;

    float hb[8];
    if (mode == 0) {
#pragma unroll
        for (int i = 0; i < 8; i++) hb[i] = LW2;
    } else {
        float4 p0 = *(const float4*)&hr_pot[c0 + j0];
        float4 p1 = *(const float4*)&hr_pot[c0 + j1];
        hb[0] = fmaf(p0.x, ie2, LW2); hb[1] = fmaf(p0.y, ie2, LW2);
        hb[2] = fmaf(p0.z, ie2, LW2); hb[3] = fmaf(p0.w, ie2, LW2);
        hb[4] = fmaf(p1.x, ie2, LW2); hb[5] = fmaf(p1.y, ie2, LW2);
        hb[6] = fmaf(p1.z, ie2, LW2); hb[7] = fmaf(p1.w, ie2, LW2);
    }

    float mc[8], sc[8];
#pragma unroll
    for (int i = 0; i < 8; i++) { mc[i] = SENT; sc[i] = 0.0f; }

#pragma unroll 2
    for (int g = 0; g < 16; g++) {
        int rl = wp + (g << 3);
        int r = r0 + rl;
        float ha = (mode == 0) ? LW2 : fmaf(hc_pot[r], ie2, LW2);

        const float* Crow = M + (size_t)r * NPTS + c0;
        float4 ca = *(const float4*)&Crow[j0];
        float4 cb = *(const float4*)&Crow[j1];

        // row direction: lane-local max + sum over 8 elements (1 exp/elt)
        float t[8];
        t[0] = fmaf(-ie2, ca.x, hb[0]); t[1] = fmaf(-ie2, ca.y, hb[1]);
        t[2] = fmaf(-ie2, ca.z, hb[2]); t[3] = fmaf(-ie2, ca.w, hb[3]);
        t[4] = fmaf(-ie2, cb.x, hb[4]); t[5] = fmaf(-ie2, cb.y, hb[5]);
        t[6] = fmaf(-ie2, cb.z, hb[6]); t[7] = fmaf(-ie2, cb.w, hb[7]);
        float lm = fmaxf(fmaxf(fmaxf(t[0], t[1]), fmaxf(t[2], t[3])),
                         fmaxf(fmaxf(t[4], t[5]), fmaxf(t[6], t[7])));
        float ls = 0.0f;
#pragma unroll
        for (int i = 0; i < 8; i++) ls += exp2f(t[i] - lm);
        smM[rl][lane] = lm;
        smS[rl][lane] = ls;

        // col direction: thread-local online state per fixed column
        lse_upd(mc[0], sc[0], fmaf(-ie2, ca.x, ha));
        lse_upd(mc[1], sc[1], fmaf(-ie2, ca.y, ha));
        lse_upd(mc[2], sc[2], fmaf(-ie2, ca.z, ha));
        lse_upd(mc[3], sc[3], fmaf(-ie2, ca.w, ha));
        lse_upd(mc[4], sc[4], fmaf(-ie2, cb.x, ha));
        lse_upd(mc[5], sc[5], fmaf(-ie2, cb.y, ha));
        lse_upd(mc[6], sc[6], fmaf(-ie2, cb.z, ha));
        lse_upd(mc[7], sc[7], fmaf(-ie2, cb.w, ha));
    }
    __syncthreads();

    // row merge: 2 threads per row, each merges 16 lane partials, pair via shfl
    {
        int row = tid >> 1, base = (tid & 1) << 4;
        float mm = smM[row][base], ss = smS[row][base];
#pragma unroll
        for (int k = 1; k < 16; k++) lse_mrg(mm, ss, smM[row][base + k], smS[row][base + k]);
        float mo = __shfl_xor_sync(0xFFFFFFFFu, mm, 1);
        float so = __shfl_xor_sync(0xFFFFFFFFu, ss, 1);
        lse_mrg(mm, ss, mo, so);
        if (!(tid & 1)) {
            g_Rm[mat][J][r0 + row] = mm;
            g_Rs[mat][J][r0 + row] = ss;
        }
    }
    __syncthreads();

    // col merge: 8 warps' states -> one partial per column (reuse smem)
    float (*cmm)[256] = (float(*)[256])&smM[0][0];
    float (*cms)[256] = (float(*)[256])&smS[0][0];
#pragma unroll
    for (int i = 0; i < 4; i++) {
        cmm[wp][j0 + i] = mc[i];     cms[wp][j0 + i] = sc[i];
        cmm[wp][j1 + i] = mc[4 + i]; cms[wp][j1 + i] = sc[4 + i];
    }
    __syncthreads();
    float mm = cmm[0][tid], ss = cms[0][tid];
#pragma unroll
    for (int w = 1; w < 8; w++) lse_mrg(mm, ss, cmm[w][tid], cms[w][tid]);
    g_Km[mat][I][c0 + tid] = mm;
    g_Ks[mat][I][c0 + tid] = ss;
}

// ---------------------------------------------------------------------------
// Parallel merge: warp per output. 4 groups x 4096 outputs = 16384 warps.
// group 0: f_ba (xy rows, 16 slots); 1: g_ab (xy cols, 32 slots);
// 2: f_aa (xx: 16-c row slots + 2c col slots); 3: g_bb (yy, same).
// ---------------------------------------------------------------------------
__global__ __launch_bounds__(256) void merge_k(int cur, int nxt,
                                               float negEpsLn2, int mode) {
    int gw = blockIdx.x * 8 + (threadIdx.x >> 5);
    int lane = threadIdx.x & 31;
    int group = gw >> 12;
    int r = gw & (NPTS - 1);

    float m = SENT, s = 0.0f;
    if (group == 0) {
        if (lane < 16) { m = g_Rm[0][lane][r]; s = g_Rs[0][lane][r]; }
    } else if (group == 1) {
        m = g_Km[0][lane][r]; s = g_Ks[0][lane][r];
    } else {
        int mt = group - 1;          // 1 = xx, 2 = yy
        int c = r >> 8;
        int nrow = 16 - c;
        if (lane < nrow)              { m = g_Rm[mt][c + lane][r];    s = g_Rs[mt][c + lane][r]; }
        else if (lane < nrow + 2 * c) { m = g_Km[mt][lane - nrow][r]; s = g_Ks[mt][lane - nrow][r]; }
    }
#pragma unroll
    for (int off = 16; off; off >>= 1) {
        float mo = __shfl_xor_sync(0xFFFFFFFFu, m, off);
        float so = __shfl_xor_sync(0xFFFFFFFFu, s, off);
        lse_mrg(m, s, mo, so);
    }
    if (lane == 0) {
        float ft = negEpsLn2 * (m + log2f(s));
        if (mode == 0)      g_pot[nxt][group][r] = ft;
        else if (mode == 1) g_pot[nxt][group][r] = 0.5f * (g_pot[cur][group][r] + ft);
        else                g_fin[group][r] = ft;
    }
}

// ---------------------------------------------------------------------------
__global__ void reduce_k(float* __restrict__ out) {
    __shared__ float red[256];
    int tid = threadIdx.x;
    float s = 0.0f;
    for (int j = tid; j < NPTS; j += 256)
        s += (g_fin[0][j] - g_fin[2][j]) + (g_fin[1][j] - g_fin[3][j]);
    red[tid] = s;
    __syncthreads();
#pragma unroll
    for (int k = 128; k > 0; k >>= 1) {
        if (tid < k) red[tid] += red[tid + k];
        __syncthreads();
    }
    if (tid == 0) out[0] = red[0] * (1.0f / (float)NPTS);
}

// ---------------------------------------------------------------------------
extern "C" void kernel_launch(void* const* d_in, const int* in_sizes, int n_in,
                              void* d_out, int out_size) {
    const float* x = (const float*)d_in[0];
    const float* y = (const float*)d_in[1];
    float* out = (float*)d_out;

    double eps_list[40];
    int ne = 0;
    eps_list[ne++] = 400.0;
    {
        double start = 2.0 * log(20.0);
        double stop  = 2.0 * log(0.01);
        double step  = 2.0 * log(0.7);
        for (int k = 0;; k++) {
            double v = start + (double)k * step;
            if (!(v > stop)) break;
            eps_list[ne++] = exp(v);
        }
    }
    eps_list[ne++] = 1e-4;

    const int NB = 512 + 2 * 272;     // 1056 tile blocks
    const int MB = (4 * NPTS) / 8 / 32 * 32 / 32;  // 16384 warps / 8 = 2048 blocks
    (void)MB;

    norms_k<<<(2 * NPTS + 255) / 256, 256>>>(x, y);
    dim3 gg(64, 64), bb(16, 16);
    cost_k<<<gg, bb>>>(x, y, 0);   // C_xy  (full)
    cost_k<<<gg, bb>>>(x, x, 1);   // C_xx  (upper block-triangle only)
    cost_k<<<gg, bb>>>(y, y, 2);   // C_yy

    // init at eps_list[0] (h = log_w)
    {
        float eps = (float)eps_list[0];
        float ie2 = (1.0f / eps) * LOG2E_F;
        big_k<<<NB, 256>>>(0, ie2, 0);
        merge_k<<<2048, 256>>>(0, 0, -eps * LN2_F, 0);
    }

    // annealing loop (double-buffered potentials)
    int cur = 0;
    for (int it = 0; it < ne; it++) {
        float eps = (float)eps_list[it];
        float ie2 = (1.0f / eps) * LOG2E_F;
        big_k<<<NB, 256>>>(cur, ie2, 1);
        merge_k<<<2048, 256>>>(cur, cur ^ 1, -eps * LN2_F, 1);
        cur ^= 1;
    }

    // final extrapolation at eps = blur^p
    {
        float eps = (float)eps_list[ne - 1];
        float ie2 = (1.0f / eps) * LOG2E_F;
        big_k<<<NB, 256>>>(cur, ie2, 2);
        merge_k<<<2048, 256>>>(cur, 0, -eps * LN2_F, 2);
    }

    reduce_k<<<1, 256>>>(out);
}